// round 15
// baseline (speedup 1.0000x reference)
#include <cuda_runtime.h>
#include <cuda_fp16.h>
#include <cstdint>

// ---------------- problem constants ----------------
#define B   512
#define NN  21
#define II  256
#define HH  1024
#define FH  4096          // 4*HH
#define KK  1280          // II + HH
#define EPS 1e-12f

// ---------------- GEMM tiling ----------------
#define TM 128
#define TN 128            // one gate x one 128-h phase block per CTA
#define TK 32
#define NSTAGE 5
#define NCHUNK (KK / TK)
#define PADB 80

#define A_STAGE_B (TM * PADB)          // 10240
#define B_STAGE_B (TN * PADB)          // 10240
#define STAGE_B   (A_STAGE_B + B_STAGE_B)
#define SM_BYTES  (NSTAGE * STAGE_B)   // 102400

// cvt region sizes in 16-element units
#define N16_WIH (5 * FH * II / 16)
#define N16_WHH (5 * FH * HH / 16)
#define N16_IN  (B * NN * II / 16)
#define N16_HX  (B * NN * HH / 16)
#define N16_TOT (N16_WIH + N16_WHH + N16_IN + N16_HX)
#define CVT_BLOCKS ((N16_TOT + 255) / 256)

// ---------------- scratch ----------------
__device__ __half  g_gates_h[(size_t)B * NN * FH];
__device__ __half2 g_gx2[NN * NN];
__device__ __half  g_wih_h[(size_t)5 * FH * II];
__device__ __half  g_whh_h[(size_t)5 * FH * HH];
__device__ __half  g_in_h[(size_t)B * NN * II];
__device__ __half  g_hx_h[(size_t)B * NN * HH];

// ---------------- helpers ----------------
__device__ __forceinline__ uint32_t smem_u32(const void* p) {
    uint32_t a;
    asm("{ .reg .u64 t; cvta.to.shared.u64 t, %1; cvt.u32.u64 %0, t; }" : "=r"(a) : "l"(p));
    return a;
}
__device__ __forceinline__ void cp16(uint32_t saddr, const void* gptr) {
    asm volatile("cp.async.cg.shared.global [%0], [%1], 16;" :: "r"(saddr), "l"(gptr));
}
__device__ __forceinline__ void ldsm4(uint32_t* r, uint32_t saddr) {
    asm volatile("ldmatrix.sync.aligned.m8n8.x4.shared.b16 {%0,%1,%2,%3}, [%4];"
                 : "=r"(r[0]), "=r"(r[1]), "=r"(r[2]), "=r"(r[3]) : "r"(saddr));
}
__device__ __forceinline__ void mma16(float* c, const uint32_t* a, const uint32_t* b) {
    asm volatile(
        "mma.sync.aligned.m16n8k16.row.col.f32.f16.f16.f32 "
        "{%0,%1,%2,%3}, {%4,%5,%6,%7}, {%8,%9}, {%0,%1,%2,%3};"
        : "+f"(c[0]), "+f"(c[1]), "+f"(c[2]), "+f"(c[3])
        : "r"(a[0]), "r"(a[1]), "r"(a[2]), "r"(a[3]), "r"(b[0]), "r"(b[1]));
}
__device__ __forceinline__ float tanh_a(float x) {
    float r;
    asm("tanh.approx.f32 %0, %1;" : "=f"(r) : "f"(x));
    return r;
}
__device__ __forceinline__ float fsig(float x) {
    return fmaf(tanh_a(0.5f * x), 0.5f, 0.5f);
}
__device__ __forceinline__ float phase_of(int h) {
    return floorf((float)h / (float)(HH - 1) * 8.0f + 1.0f);
}
// does the 128-h block starting at h0 contain ANY mask=1 position?
__device__ __forceinline__ bool block_active(int h0, float t1) {
    int p0 = (int)phase_of(h0);
    int h1 = h0 + 127; if (h1 > HH - 1) h1 = HH - 1;
    int p1 = (int)phase_of(h1);
#pragma unroll 2
    for (int p = p0; p <= p1; p++)
        if (fmodf(t1, (float)p) < 0.01f) return true;
    return false;
}
__device__ __forceinline__ uint4 cvt8(float4 v0, float4 v1) {
    __half2 h0 = __floats2half2_rn(v0.x, v0.y);
    __half2 h1 = __floats2half2_rn(v0.z, v0.w);
    __half2 h2 = __floats2half2_rn(v1.x, v1.y);
    __half2 h3 = __floats2half2_rn(v1.z, v1.w);
    uint4 o;
    o.x = *(uint32_t*)&h0; o.y = *(uint32_t*)&h1;
    o.z = *(uint32_t*)&h2; o.w = *(uint32_t*)&h3;
    return o;
}

// ---------------- kernel: fused fp32->fp16 conversion (16 elems/thr) + gx ----------------
__global__ void cvt_all_kernel(const float4* __restrict__ wih, const float4* __restrict__ whh,
                               const float4* __restrict__ in,  const float4* __restrict__ hx,
                               uint4* __restrict__ o_wih, uint4* __restrict__ o_whh,
                               uint4* __restrict__ o_in,  uint4* __restrict__ o_hx,
                               const float* __restrict__ G, float* __restrict__ gx_out,
                               const int* __restrict__ tptr) {
    if (blockIdx.x == CVT_BLOCKS) {
        __shared__ float sG[NN * NN];
        __shared__ float den[NN];
        __shared__ float den2[NN];
        int tid = threadIdx.x;
        for (int i = tid; i < NN * NN; i += blockDim.x) sG[i] = G[i];
        __syncthreads();
        if (tid < NN) {
            float s = 0.f;
            for (int j = 0; j < NN; j++) s += fabsf(sG[tid * NN + j]);
            den[tid] = fmaxf(s, EPS);
        }
        __syncthreads();
        for (int i = tid; i < NN * NN; i += blockDim.x) sG[i] = sG[i] / den[i / NN];
        __syncthreads();
        if (tid < NN) {
            float s = 0.f;
            for (int j = 0; j < NN; j++) s += fabsf(sG[tid * NN + j]);
            den2[tid] = fmaxf(s, EPS);
        }
        __syncthreads();
        for (int i = tid; i < NN * NN; i += blockDim.x) {
            float w = sG[i];
            g_gx2[i]  = __float2half2_rn(w);
            gx_out[i] = w / den2[i / NN];
        }
        return;
    }

    int i = blockIdx.x * blockDim.x + threadIdx.x;   // 16-elem unit index
    if (i >= N16_TOT) return;
    const float t1 = (float)(*tptr) + 1.0f;
    const float4* s;
    uint4* d;
    int j = i;   // unit index within region
    if (j < N16_WIH) {
        // II=256 -> 16 units per weight row
        int ol = (j >> 4) & (FH - 1);
        int gate = ol >> 10;
        if (gate != 3 && !block_active((ol & 1023) & ~127, t1)) return;
        s = wih; d = o_wih;
    } else {
        j -= N16_WIH;
        if (j < N16_WHH) {
            // HH=1024 -> 64 units per weight row
            int ol = (j >> 6) & (FH - 1);
            int gate = ol >> 10;
            if (gate != 3 && !block_active((ol & 1023) & ~127, t1)) return;
            s = whh; d = o_whh;
        } else {
            j -= N16_WHH;
            if (j < N16_IN) { s = in; d = o_in; }
            else { j -= N16_IN; s = hx; d = o_hx; }
        }
    }
    // 16 floats in, 2x uint4 out; 4 independent float4 loads for MLP
    float4 v0 = s[4 * j];
    float4 v1 = s[4 * j + 1];
    float4 v2 = s[4 * j + 2];
    float4 v3 = s[4 * j + 3];
    d[2 * j]     = cvt8(v0, v1);
    d[2 * j + 1] = cvt8(v2, v3);
}

// ---------------- kernel 1: fp16 mma.sync gates GEMM, TN=128, 256 thr, 2 CTA/SM ----------------
__global__ __launch_bounds__(256, 2)
void gates_gemm(const float* __restrict__ bhh, const int* __restrict__ ntypes,
                const int* __restrict__ tptr) {
    const int bo = blockIdx.x * TN;
    {
        const float t1 = (float)(*tptr) + 1.0f;
        const int gate = bo >> 10;
        if (gate != 3 && !block_active(bo & 1023, t1)) return;  // uniform exit
    }

    extern __shared__ char smc[];
    const int tid  = threadIdx.x;
    const int lane = tid & 31;
    const int wid  = tid >> 5;

    const int n  = blockIdx.z;
    const int bm = blockIdx.y * TM;
    const int nt = ntypes[n];
    const __half* wih = g_wih_h + (size_t)nt * FH * II;
    const __half* whh = g_whh_h + (size_t)nt * FH * HH;

    const uint32_t sb = smem_u32(smc);

    // warp tiling: 4 (m) x 2 (n), warp tile 32x64
    const int wm = (wid & 3) * 32;
    const int wn = (wid >> 2) * 64;

    const uint32_t aL = (uint32_t)((((lane >> 3) & 1) * 8 + (lane & 7)) * PADB + (lane >> 4) * 16);
    const uint32_t bL = (uint32_t)((((lane >> 4) & 1) * 8 + (lane & 7)) * PADB + ((lane >> 3) & 1) * 16);

    float acc[2][8][4];
#pragma unroll
    for (int i = 0; i < 2; i++)
#pragma unroll
        for (int j = 0; j < 8; j++)
#pragma unroll
            for (int v = 0; v < 4; v++) acc[i][j][v] = 0.f;

    auto load_stage = [&](int kt) {
        const int s  = kt % NSTAGE;
        const int k0 = kt * TK;
        const uint32_t ab = sb + (uint32_t)(s * STAGE_B);
        const uint32_t bb = ab + (uint32_t)A_STAGE_B;
#pragma unroll
        for (int i = 0; i < 2; i++) {
            int f = tid + i * 256;
            int r = f >> 2, c = f & 3;
            int k = k0 + c * 8;
            const __half* src = (k < II)
                ? g_in_h + ((size_t)(bm + r) * NN + n) * II + k
                : g_hx_h + ((size_t)(bm + r) * NN + n) * HH + (k - II);
            cp16(ab + (uint32_t)(r * PADB + c * 16), src);
        }
#pragma unroll
        for (int i = 0; i < 2; i++) {
            int f = tid + i * 256;
            int r = f >> 2, c = f & 3;
            int k = k0 + c * 8;
            const __half* src = (k < II)
                ? wih + (size_t)(bo + r) * II + k
                : whh + (size_t)(bo + r) * HH + (k - II);
            cp16(bb + (uint32_t)(r * PADB + c * 16), src);
        }
    };

#pragma unroll
    for (int s = 0; s < NSTAGE; s++) {
        load_stage(s);
        asm volatile("cp.async.commit_group;" ::: "memory");
    }

    for (int kt = 0; kt < NCHUNK; kt++) {
        asm volatile("cp.async.wait_group %0;" :: "n"(NSTAGE - 1) : "memory");
        __syncthreads();

        const int s = kt % NSTAGE;
        const uint32_t sAb = sb + (uint32_t)(s * STAGE_B);
        const uint32_t sBb = sAb + (uint32_t)A_STAGE_B;

#pragma unroll
        for (int ks = 0; ks < TK / 16; ks++) {
            const uint32_t kb = (uint32_t)(ks * 32);
            uint32_t af[2][4];
#pragma unroll
            for (int mi = 0; mi < 2; mi++)
                ldsm4(af[mi], sAb + (uint32_t)((wm + mi * 16) * PADB) + kb + aL);
            uint32_t bq[4][4];
#pragma unroll
            for (int np = 0; np < 4; np++)
                ldsm4(bq[np], sBb + (uint32_t)((wn + np * 16) * PADB) + kb + bL);
#pragma unroll
            for (int mi = 0; mi < 2; mi++)
#pragma unroll
                for (int ni = 0; ni < 8; ni++)
                    mma16(acc[mi][ni], af[mi], &bq[ni >> 1][(ni & 1) * 2]);
        }
        __syncthreads();
        if (kt + NSTAGE < NCHUNK) load_stage(kt + NSTAGE);
        asm volatile("cp.async.commit_group;" ::: "memory");
    }

    const int lr = lane >> 2;
    const int lq = lane & 3;
    const float* brow = bhh + (size_t)nt * FH + bo;
#pragma unroll
    for (int mi = 0; mi < 2; mi++) {
        int r0 = wm + mi * 16 + lr;
        __half* out0 = g_gates_h + ((size_t)(bm + r0)     * NN + n) * FH + bo;
        __half* out1 = g_gates_h + ((size_t)(bm + r0 + 8) * NN + n) * FH + bo;
#pragma unroll
        for (int ni = 0; ni < 8; ni++) {
            int col = wn + ni * 8 + lq * 2;
            float2 bv = *(const float2*)(brow + col);
            __half2 v0 = __floats2half2_rn(acc[mi][ni][0] + bv.x, acc[mi][ni][1] + bv.y);
            __half2 v1 = __floats2half2_rn(acc[mi][ni][2] + bv.x, acc[mi][ni][3] + bv.y);
            *(__half2*)(out0 + col) = v0;
            *(__half2*)(out1 + col) = v1;
        }
    }
}

// ---------------- kernel 2: graph mix + LSTM; clockwork skipping + streaming hints ----------------
__global__ __launch_bounds__(128)
void pass2(const float* __restrict__ cx, const int* __restrict__ tptr,
           float* __restrict__ hy, float* __restrict__ cyo) {
    __shared__ __half2 sgx[NN * NN];
    const int tid = threadIdx.x;
    for (int i = tid; i < NN * NN; i += 128) sgx[i] = g_gx2[i];
    __syncthreads();

    const int b = blockIdx.y;
    const int h = blockIdx.x * 256 + tid * 2;

    const float t1  = (float)(*tptr) + 1.0f;
    const float ph0 = phase_of(h);
    const float ph1 = phase_of(h + 1);
    const float mk0 = (fmodf(t1, ph0) < 0.01f) ? 1.0f : 0.0f;
    const float mk1 = (fmodf(t1, ph1) < 0.01f) ? 1.0f : 0.0f;
    const bool  active = (mk0 + mk1) > 0.f;

    const __half* gbase = g_gates_h + (size_t)b * NN * FH + h;

    __half2 rg3[NN];
#pragma unroll
    for (int nI = 0; nI < NN; nI++)
        rg3[nI] = *(const __half2*)(gbase + (size_t)nI * FH + 3 * HH);

    if (active) {
        __half2 rg0[NN], rg1[NN], rg2[NN];
#pragma unroll
        for (int nI = 0; nI < NN; nI++) {
            const __half* p = gbase + (size_t)nI * FH;
            rg0[nI] = *(const __half2*)(p);
            rg1[nI] = *(const __half2*)(p + HH);
            rg2[nI] = *(const __half2*)(p + 2 * HH);
        }
#pragma unroll 1
        for (int m = 0; m < NN; m++) {
            const __half2* wrow = &sgx[m * NN];
            __half2 z = __float2half2_rn(0.f);
            __half2 i0 = z, i1 = z, f0 = z, f1 = z, c0 = z, c1 = z, o0 = z, o1 = z;
#pragma unroll
            for (int nI = 0; nI < NN; nI++) {
                __half2 w = wrow[nI];
                if (nI & 1) {
                    i1 = __hfma2(w, rg0[nI], i1);
                    f1 = __hfma2(w, rg1[nI], f1);
                    c1 = __hfma2(w, rg2[nI], c1);
                    o1 = __hfma2(w, rg3[nI], o1);
                } else {
                    i0 = __hfma2(w, rg0[nI], i0);
                    f0 = __hfma2(w, rg1[nI], f0);
                    c0 = __hfma2(w, rg2[nI], c0);
                    o0 = __hfma2(w, rg3[nI], o0);
                }
            }
            float2 ig = __half22float2(__hadd2(i0, i1));
            float2 fg = __half22float2(__hadd2(f0, f1));
            float2 cg = __half22float2(__hadd2(c0, c1));
            float2 og = __half22float2(__hadd2(o0, o1));

            size_t idx = ((size_t)b * NN + m) * HH + h;
            float2 cxv = __ldcs((const float2*)(cx + idx));

            float isx = fsig(ig.x), isy = fsig(ig.y);
            float fsx = fsig(fg.x), fsy = fsig(fg.y);
            float ctx = tanh_a(cg.x), cty = tanh_a(cg.y);
            float osx = fsig(og.x), osy = fsig(og.y);

            float cyx = mk0 * (fsx * cxv.x + isx * ctx) + (1.0f - mk0) * cxv.x;
            float cyy = mk1 * (fsy * cxv.y + isy * cty) + (1.0f - mk1) * cxv.y;
            float hyx = osx * tanh_a(cyx);
            float hyy = osy * tanh_a(cyy);

            __stcs((float2*)(hy + idx),  make_float2(hyx, hyy));
            __stcs((float2*)(cyo + idx), make_float2(cyx, cyy));
        }
    } else {
#pragma unroll 1
        for (int m = 0; m < NN; m++) {
            const __half2* wrow = &sgx[m * NN];
            __half2 z = __float2half2_rn(0.f);
            __half2 o0 = z, o1 = z;
#pragma unroll
            for (int nI = 0; nI < NN; nI++) {
                __half2 w = wrow[nI];
                if (nI & 1) o1 = __hfma2(w, rg3[nI], o1);
                else        o0 = __hfma2(w, rg3[nI], o0);
            }
            float2 og = __half22float2(__hadd2(o0, o1));

            size_t idx = ((size_t)b * NN + m) * HH + h;
            float2 cxv = __ldcs((const float2*)(cx + idx));

            float hyx = fsig(og.x) * tanh_a(cxv.x);
            float hyy = fsig(og.y) * tanh_a(cxv.y);

            __stcs((float2*)(hy + idx),  make_float2(hyx, hyy));
            __stcs((float2*)(cyo + idx), cxv);
        }
    }
}

// ---------------- launch ----------------
extern "C" void kernel_launch(void* const* d_in, const int* in_sizes, int n_in,
                              void* d_out, int out_size) {
    const float* input  = (const float*)d_in[0];
    const float* hx     = (const float*)d_in[1];
    const float* cx     = (const float*)d_in[2];
    const float* G      = (const float*)d_in[3];
    const float* wih    = (const float*)d_in[4];
    const float* whh    = (const float*)d_in[5];
    const float* bhh    = (const float*)d_in[6];
    const int*   ntypes = (const int*)d_in[7];
    const int*   tptr   = (const int*)d_in[8];

    float* hy  = (float*)d_out;
    float* cy  = hy + (size_t)B * NN * HH;
    float* gxo = cy + (size_t)B * NN * HH;

    cudaFuncSetAttribute(gates_gemm, cudaFuncAttributeMaxDynamicSharedMemorySize, SM_BYTES);

    void *p_wih, *p_whh, *p_in, *p_hx;
    cudaGetSymbolAddress(&p_wih, g_wih_h);
    cudaGetSymbolAddress(&p_whh, g_whh_h);
    cudaGetSymbolAddress(&p_in,  g_in_h);
    cudaGetSymbolAddress(&p_hx,  g_hx_h);

    cvt_all_kernel<<<CVT_BLOCKS + 1, 256>>>(
        (const float4*)wih, (const float4*)whh, (const float4*)input, (const float4*)hx,
        (uint4*)p_wih, (uint4*)p_whh, (uint4*)p_in, (uint4*)p_hx,
        G, gxo, tptr);

    dim3 grid1(FH / TN, B / TM, NN);   // (32, 4, 21)
    gates_gemm<<<grid1, 256, SM_BYTES>>>(bhh, ntypes, tptr);

    dim3 grid2(HH / 256, B);           // (4, 512)
    pass2<<<grid2, 128>>>(cx, tptr, hy, cy);
}

// round 16
// speedup vs baseline: 1.0299x; 1.0299x over previous
#include <cuda_runtime.h>
#include <cuda_fp16.h>
#include <cstdint>

// ---------------- problem constants ----------------
#define B   512
#define NN  21
#define II  256
#define HH  1024
#define FH  4096          // 4*HH
#define KK  1280          // II + HH
#define EPS 1e-12f

// ---------------- GEMM tiling ----------------
#define TM 128
#define TN 128            // one gate x one 128-h phase block per CTA
#define TK 32
#define NSTAGE 4
#define NCHUNK (KK / TK)
#define PADB 80

#define A_STAGE_B (TM * PADB)          // 10240
#define B_STAGE_B (TN * PADB)          // 10240
#define STAGE_B   (A_STAGE_B + B_STAGE_B)
#define SM_BYTES  (NSTAGE * STAGE_B)   // 81920

// cvt region sizes in 16-element units
#define N16_WIH (5 * FH * II / 16)
#define N16_WHH (5 * FH * HH / 16)
#define N16_IN  (B * NN * II / 16)
#define N16_HX  (B * NN * HH / 16)
#define N16_TOT (N16_WIH + N16_WHH + N16_IN + N16_HX)
#define CVT_BLOCKS ((N16_TOT + 255) / 256)

// ---------------- scratch ----------------
__device__ __half  g_gates_h[(size_t)B * NN * FH];
__device__ __half2 g_gx2[NN * NN];
__device__ __half  g_wih_h[(size_t)5 * FH * II];
__device__ __half  g_whh_h[(size_t)5 * FH * HH];
__device__ __half  g_in_h[(size_t)B * NN * II];
__device__ __half  g_hx_h[(size_t)B * NN * HH];

// ---------------- helpers ----------------
__device__ __forceinline__ uint32_t smem_u32(const void* p) {
    uint32_t a;
    asm("{ .reg .u64 t; cvta.to.shared.u64 t, %1; cvt.u32.u64 %0, t; }" : "=r"(a) : "l"(p));
    return a;
}
__device__ __forceinline__ void cp16(uint32_t saddr, const void* gptr) {
    asm volatile("cp.async.cg.shared.global [%0], [%1], 16;" :: "r"(saddr), "l"(gptr));
}
__device__ __forceinline__ void ldsm4(uint32_t* r, uint32_t saddr) {
    asm volatile("ldmatrix.sync.aligned.m8n8.x4.shared.b16 {%0,%1,%2,%3}, [%4];"
                 : "=r"(r[0]), "=r"(r[1]), "=r"(r[2]), "=r"(r[3]) : "r"(saddr));
}
__device__ __forceinline__ void mma16(float* c, const uint32_t* a, const uint32_t* b) {
    asm volatile(
        "mma.sync.aligned.m16n8k16.row.col.f32.f16.f16.f32 "
        "{%0,%1,%2,%3}, {%4,%5,%6,%7}, {%8,%9}, {%0,%1,%2,%3};"
        : "+f"(c[0]), "+f"(c[1]), "+f"(c[2]), "+f"(c[3])
        : "r"(a[0]), "r"(a[1]), "r"(a[2]), "r"(a[3]), "r"(b[0]), "r"(b[1]));
}
__device__ __forceinline__ float tanh_a(float x) {
    float r;
    asm("tanh.approx.f32 %0, %1;" : "=f"(r) : "f"(x));
    return r;
}
__device__ __forceinline__ float fsig(float x) {
    return fmaf(tanh_a(0.5f * x), 0.5f, 0.5f);
}
__device__ __forceinline__ float phase_of(int h) {
    return floorf((float)h / (float)(HH - 1) * 8.0f + 1.0f);
}
__device__ __forceinline__ bool block_active(int h0, float t1) {
    int p0 = (int)phase_of(h0);
    int h1 = h0 + 127; if (h1 > HH - 1) h1 = HH - 1;
    int p1 = (int)phase_of(h1);
#pragma unroll 2
    for (int p = p0; p <= p1; p++)
        if (fmodf(t1, (float)p) < 0.01f) return true;
    return false;
}
__device__ __forceinline__ uint4 cvt8(float4 v0, float4 v1) {
    __half2 h0 = __floats2half2_rn(v0.x, v0.y);
    __half2 h1 = __floats2half2_rn(v0.z, v0.w);
    __half2 h2 = __floats2half2_rn(v1.x, v1.y);
    __half2 h3 = __floats2half2_rn(v1.z, v1.w);
    uint4 o;
    o.x = *(uint32_t*)&h0; o.y = *(uint32_t*)&h1;
    o.z = *(uint32_t*)&h2; o.w = *(uint32_t*)&h3;
    return o;
}

// ---------------- kernel: fused fp32->fp16 conversion (16 elems/thr) + gx ----------------
__global__ void cvt_all_kernel(const float4* __restrict__ wih, const float4* __restrict__ whh,
                               const float4* __restrict__ in,  const float4* __restrict__ hx,
                               uint4* __restrict__ o_wih, uint4* __restrict__ o_whh,
                               uint4* __restrict__ o_in,  uint4* __restrict__ o_hx,
                               const float* __restrict__ G, float* __restrict__ gx_out,
                               const int* __restrict__ tptr) {
    if (blockIdx.x == CVT_BLOCKS) {
        __shared__ float sG[NN * NN];
        __shared__ float den[NN];
        __shared__ float den2[NN];
        int tid = threadIdx.x;
        for (int i = tid; i < NN * NN; i += blockDim.x) sG[i] = G[i];
        __syncthreads();
        if (tid < NN) {
            float s = 0.f;
            for (int j = 0; j < NN; j++) s += fabsf(sG[tid * NN + j]);
            den[tid] = fmaxf(s, EPS);
        }
        __syncthreads();
        for (int i = tid; i < NN * NN; i += blockDim.x) sG[i] = sG[i] / den[i / NN];
        __syncthreads();
        if (tid < NN) {
            float s = 0.f;
            for (int j = 0; j < NN; j++) s += fabsf(sG[tid * NN + j]);
            den2[tid] = fmaxf(s, EPS);
        }
        __syncthreads();
        for (int i = tid; i < NN * NN; i += blockDim.x) {
            float w = sG[i];
            g_gx2[i]  = __float2half2_rn(w);
            gx_out[i] = w / den2[i / NN];
        }
        return;
    }

    int i = blockIdx.x * blockDim.x + threadIdx.x;
    if (i >= N16_TOT) return;
    const float t1 = (float)(*tptr) + 1.0f;
    const float4* s;
    uint4* d;
    int j = i;
    if (j < N16_WIH) {
        int ol = (j >> 4) & (FH - 1);
        int gate = ol >> 10;
        if (gate != 3 && !block_active((ol & 1023) & ~127, t1)) return;
        s = wih; d = o_wih;
    } else {
        j -= N16_WIH;
        if (j < N16_WHH) {
            int ol = (j >> 6) & (FH - 1);
            int gate = ol >> 10;
            if (gate != 3 && !block_active((ol & 1023) & ~127, t1)) return;
            s = whh; d = o_whh;
        } else {
            j -= N16_WHH;
            if (j < N16_IN) { s = in; d = o_in; }
            else { j -= N16_IN; s = hx; d = o_hx; }
        }
    }
    float4 v0 = s[4 * j];
    float4 v1 = s[4 * j + 1];
    float4 v2 = s[4 * j + 2];
    float4 v3 = s[4 * j + 3];
    d[2 * j]     = cvt8(v0, v1);
    d[2 * j + 1] = cvt8(v2, v3);
}

// ---------------- kernel 1: fp16 mma.sync gates GEMM; 1-sync multistage schedule ----------------
__global__ __launch_bounds__(256, 2)
void gates_gemm(const float* __restrict__ bhh, const int* __restrict__ ntypes,
                const int* __restrict__ tptr) {
    const int bo = blockIdx.x * TN;
    {
        const float t1 = (float)(*tptr) + 1.0f;
        const int gate = bo >> 10;
        if (gate != 3 && !block_active(bo & 1023, t1)) return;  // uniform exit
    }

    extern __shared__ char smc[];
    const int tid  = threadIdx.x;
    const int lane = tid & 31;
    const int wid  = tid >> 5;

    const int n  = blockIdx.z;
    const int bm = blockIdx.y * TM;
    const int nt = ntypes[n];
    const __half* wih = g_wih_h + (size_t)nt * FH * II;
    const __half* whh = g_whh_h + (size_t)nt * FH * HH;

    const uint32_t sb = smem_u32(smc);

    const int wm = (wid & 3) * 32;
    const int wn = (wid >> 2) * 64;

    const uint32_t aL = (uint32_t)((((lane >> 3) & 1) * 8 + (lane & 7)) * PADB + (lane >> 4) * 16);
    const uint32_t bL = (uint32_t)((((lane >> 4) & 1) * 8 + (lane & 7)) * PADB + ((lane >> 3) & 1) * 16);

    float acc[2][8][4];
#pragma unroll
    for (int i = 0; i < 2; i++)
#pragma unroll
        for (int j = 0; j < 8; j++)
#pragma unroll
            for (int v = 0; v < 4; v++) acc[i][j][v] = 0.f;

    // loads k-chunk kt into smem slot `slot`
    auto load_stage = [&](int kt, int slot) {
        const int k0 = kt * TK;
        const uint32_t ab = sb + (uint32_t)(slot * STAGE_B);
        const uint32_t bb = ab + (uint32_t)A_STAGE_B;
#pragma unroll
        for (int i = 0; i < 2; i++) {
            int f = tid + i * 256;
            int r = f >> 2, c = f & 3;
            int k = k0 + c * 8;
            const __half* src = (k < II)
                ? g_in_h + ((size_t)(bm + r) * NN + n) * II + k
                : g_hx_h + ((size_t)(bm + r) * NN + n) * HH + (k - II);
            cp16(ab + (uint32_t)(r * PADB + c * 16), src);
        }
#pragma unroll
        for (int i = 0; i < 2; i++) {
            int f = tid + i * 256;
            int r = f >> 2, c = f & 3;
            int k = k0 + c * 8;
            const __half* src = (k < II)
                ? wih + (size_t)(bo + r) * II + k
                : whh + (size_t)(bo + r) * HH + (k - II);
            cp16(bb + (uint32_t)(r * PADB + c * 16), src);
        }
    };

    // prologue: fill NSTAGE-1 stages (slots 0..2)
#pragma unroll
    for (int s = 0; s < NSTAGE - 1; s++) {
        load_stage(s, s);
        asm volatile("cp.async.commit_group;" ::: "memory");
    }

    // mainloop: ONE sync per k-tile.
    // iter kt consumes slot kt%4 (loaded at iter kt-3, group already drained by
    // wait_group 2), then prefetches chunk kt+3 into slot (kt+3)%4 == (kt-1)%4,
    // which all warps finished reading last iteration (fenced by this sync).
    for (int kt = 0; kt < NCHUNK; kt++) {
        asm volatile("cp.async.wait_group %0;" :: "n"(NSTAGE - 2) : "memory");
        __syncthreads();

        const int s = kt % NSTAGE;
        const uint32_t sAb = sb + (uint32_t)(s * STAGE_B);
        const uint32_t sBb = sAb + (uint32_t)A_STAGE_B;

        // prefetch first so cp.async issues before the mma burst
        if (kt + NSTAGE - 1 < NCHUNK)
            load_stage(kt + NSTAGE - 1, (kt + NSTAGE - 1) % NSTAGE);
        asm volatile("cp.async.commit_group;" ::: "memory");

#pragma unroll
        for (int ks = 0; ks < TK / 16; ks++) {
            const uint32_t kb = (uint32_t)(ks * 32);
            uint32_t af[2][4];
#pragma unroll
            for (int mi = 0; mi < 2; mi++)
                ldsm4(af[mi], sAb + (uint32_t)((wm + mi * 16) * PADB) + kb + aL);
            uint32_t bq[4][4];
#pragma unroll
            for (int np = 0; np < 4; np++)
                ldsm4(bq[np], sBb + (uint32_t)((wn + np * 16) * PADB) + kb + bL);
#pragma unroll
            for (int mi = 0; mi < 2; mi++)
#pragma unroll
                for (int ni = 0; ni < 8; ni++)
                    mma16(acc[mi][ni], af[mi], &bq[ni >> 1][(ni & 1) * 2]);
        }
    }

    const int lr = lane >> 2;
    const int lq = lane & 3;
    const float* brow = bhh + (size_t)nt * FH + bo;
#pragma unroll
    for (int mi = 0; mi < 2; mi++) {
        int r0 = wm + mi * 16 + lr;
        __half* out0 = g_gates_h + ((size_t)(bm + r0)     * NN + n) * FH + bo;
        __half* out1 = g_gates_h + ((size_t)(bm + r0 + 8) * NN + n) * FH + bo;
#pragma unroll
        for (int ni = 0; ni < 8; ni++) {
            int col = wn + ni * 8 + lq * 2;
            float2 bv = *(const float2*)(brow + col);
            __half2 v0 = __floats2half2_rn(acc[mi][ni][0] + bv.x, acc[mi][ni][1] + bv.y);
            __half2 v1 = __floats2half2_rn(acc[mi][ni][2] + bv.x, acc[mi][ni][3] + bv.y);
            *(__half2*)(out0 + col) = v0;
            *(__half2*)(out1 + col) = v1;
        }
    }
}

// ---------------- kernel 2: graph mix + LSTM; clockwork skipping + streaming hints ----------------
__global__ __launch_bounds__(128)
void pass2(const float* __restrict__ cx, const int* __restrict__ tptr,
           float* __restrict__ hy, float* __restrict__ cyo) {
    __shared__ __half2 sgx[NN * NN];
    const int tid = threadIdx.x;
    for (int i = tid; i < NN * NN; i += 128) sgx[i] = g_gx2[i];
    __syncthreads();

    const int b = blockIdx.y;
    const int h = blockIdx.x * 256 + tid * 2;

    const float t1  = (float)(*tptr) + 1.0f;
    const float ph0 = phase_of(h);
    const float ph1 = phase_of(h + 1);
    const float mk0 = (fmodf(t1, ph0) < 0.01f) ? 1.0f : 0.0f;
    const float mk1 = (fmodf(t1, ph1) < 0.01f) ? 1.0f : 0.0f;
    const bool  active = (mk0 + mk1) > 0.f;

    const __half* gbase = g_gates_h + (size_t)b * NN * FH + h;

    __half2 rg3[NN];
#pragma unroll
    for (int nI = 0; nI < NN; nI++)
        rg3[nI] = *(const __half2*)(gbase + (size_t)nI * FH + 3 * HH);

    if (active) {
        __half2 rg0[NN], rg1[NN], rg2[NN];
#pragma unroll
        for (int nI = 0; nI < NN; nI++) {
            const __half* p = gbase + (size_t)nI * FH;
            rg0[nI] = *(const __half2*)(p);
            rg1[nI] = *(const __half2*)(p + HH);
            rg2[nI] = *(const __half2*)(p + 2 * HH);
        }
#pragma unroll 1
        for (int m = 0; m < NN; m++) {
            const __half2* wrow = &sgx[m * NN];
            __half2 z = __float2half2_rn(0.f);
            __half2 i0 = z, i1 = z, f0 = z, f1 = z, c0 = z, c1 = z, o0 = z, o1 = z;
#pragma unroll
            for (int nI = 0; nI < NN; nI++) {
                __half2 w = wrow[nI];
                if (nI & 1) {
                    i1 = __hfma2(w, rg0[nI], i1);
                    f1 = __hfma2(w, rg1[nI], f1);
                    c1 = __hfma2(w, rg2[nI], c1);
                    o1 = __hfma2(w, rg3[nI], o1);
                } else {
                    i0 = __hfma2(w, rg0[nI], i0);
                    f0 = __hfma2(w, rg1[nI], f0);
                    c0 = __hfma2(w, rg2[nI], c0);
                    o0 = __hfma2(w, rg3[nI], o0);
                }
            }
            float2 ig = __half22float2(__hadd2(i0, i1));
            float2 fg = __half22float2(__hadd2(f0, f1));
            float2 cg = __half22float2(__hadd2(c0, c1));
            float2 og = __half22float2(__hadd2(o0, o1));

            size_t idx = ((size_t)b * NN + m) * HH + h;
            float2 cxv = __ldcs((const float2*)(cx + idx));

            float isx = fsig(ig.x), isy = fsig(ig.y);
            float fsx = fsig(fg.x), fsy = fsig(fg.y);
            float ctx = tanh_a(cg.x), cty = tanh_a(cg.y);
            float osx = fsig(og.x), osy = fsig(og.y);

            float cyx = mk0 * (fsx * cxv.x + isx * ctx) + (1.0f - mk0) * cxv.x;
            float cyy = mk1 * (fsy * cxv.y + isy * cty) + (1.0f - mk1) * cxv.y;
            float hyx = osx * tanh_a(cyx);
            float hyy = osy * tanh_a(cyy);

            __stcs((float2*)(hy + idx),  make_float2(hyx, hyy));
            __stcs((float2*)(cyo + idx), make_float2(cyx, cyy));
        }
    } else {
#pragma unroll 1
        for (int m = 0; m < NN; m++) {
            const __half2* wrow = &sgx[m * NN];
            __half2 z = __float2half2_rn(0.f);
            __half2 o0 = z, o1 = z;
#pragma unroll
            for (int nI = 0; nI < NN; nI++) {
                __half2 w = wrow[nI];
                if (nI & 1) o1 = __hfma2(w, rg3[nI], o1);
                else        o0 = __hfma2(w, rg3[nI], o0);
            }
            float2 og = __half22float2(__hadd2(o0, o1));

            size_t idx = ((size_t)b * NN + m) * HH + h;
            float2 cxv = __ldcs((const float2*)(cx + idx));

            float hyx = fsig(og.x) * tanh_a(cxv.x);
            float hyy = fsig(og.y) * tanh_a(cxv.y);

            __stcs((float2*)(hy + idx),  make_float2(hyx, hyy));
            __stcs((float2*)(cyo + idx), cxv);
        }
    }
}

// ---------------- launch ----------------
extern "C" void kernel_launch(void* const* d_in, const int* in_sizes, int n_in,
                              void* d_out, int out_size) {
    const float* input  = (const float*)d_in[0];
    const float* hx     = (const float*)d_in[1];
    const float* cx     = (const float*)d_in[2];
    const float* G      = (const float*)d_in[3];
    const float* wih    = (const float*)d_in[4];
    const float* whh    = (const float*)d_in[5];
    const float* bhh    = (const float*)d_in[6];
    const int*   ntypes = (const int*)d_in[7];
    const int*   tptr   = (const int*)d_in[8];

    float* hy  = (float*)d_out;
    float* cy  = hy + (size_t)B * NN * HH;
    float* gxo = cy + (size_t)B * NN * HH;

    cudaFuncSetAttribute(gates_gemm, cudaFuncAttributeMaxDynamicSharedMemorySize, SM_BYTES);

    void *p_wih, *p_whh, *p_in, *p_hx;
    cudaGetSymbolAddress(&p_wih, g_wih_h);
    cudaGetSymbolAddress(&p_whh, g_whh_h);
    cudaGetSymbolAddress(&p_in,  g_in_h);
    cudaGetSymbolAddress(&p_hx,  g_hx_h);

    cvt_all_kernel<<<CVT_BLOCKS + 1, 256>>>(
        (const float4*)wih, (const float4*)whh, (const float4*)input, (const float4*)hx,
        (uint4*)p_wih, (uint4*)p_whh, (uint4*)p_in, (uint4*)p_hx,
        G, gxo, tptr);

    dim3 grid1(FH / TN, B / TM, NN);   // (32, 4, 21)
    gates_gemm<<<grid1, 256, SM_BYTES>>>(bhh, ntypes, tptr);

    dim3 grid2(HH / 256, B);           // (4, 512)
    pass2<<<grid2, 128>>>(cx, tptr, hy, cy);
}

// round 17
// speedup vs baseline: 1.0412x; 1.0110x over previous
#include <cuda_runtime.h>
#include <cuda_fp16.h>
#include <cstdint>

// ---------------- problem constants ----------------
#define B   512
#define NN  21
#define II  256
#define HH  1024
#define FH  4096          // 4*HH
#define KK  1280          // II + HH
#define EPS 1e-12f

// ---------------- GEMM tiling ----------------
#define TM 128
#define TN 128            // one gate x one 128-h phase block per CTA
#define TK 32
#define NSTAGE 4
#define NCHUNK (KK / TK)
#define PADB 80

#define A_STAGE_B (TM * PADB)          // 10240
#define B_STAGE_B (TN * PADB)          // 10240
#define STAGE_B   (A_STAGE_B + B_STAGE_B)
#define SM_BYTES  (NSTAGE * STAGE_B)   // 81920

// cvt region sizes in 16-element units
#define N16_WIH (5 * FH * II / 16)
#define N16_WHH (5 * FH * HH / 16)
#define N16_IN  (B * NN * II / 16)
#define N16_HX  (B * NN * HH / 16)
#define N16_TOT (N16_WIH + N16_WHH + N16_IN + N16_HX)
#define CVT_BLOCKS ((N16_TOT + 255) / 256)

// ---------------- scratch ----------------
__device__ __half  g_gates_h[(size_t)B * NN * FH];
__device__ __half2 g_gx2[NN * NN];
__device__ __half  g_wih_h[(size_t)5 * FH * II];
__device__ __half  g_whh_h[(size_t)5 * FH * HH];
__device__ __half  g_in_h[(size_t)B * NN * II];
__device__ __half  g_hx_h[(size_t)B * NN * HH];

// ---------------- helpers ----------------
__device__ __forceinline__ uint32_t smem_u32(const void* p) {
    uint32_t a;
    asm("{ .reg .u64 t; cvta.to.shared.u64 t, %1; cvt.u32.u64 %0, t; }" : "=r"(a) : "l"(p));
    return a;
}
__device__ __forceinline__ void cp16(uint32_t saddr, const void* gptr) {
    asm volatile("cp.async.cg.shared.global [%0], [%1], 16;" :: "r"(saddr), "l"(gptr));
}
__device__ __forceinline__ void ldsm4(uint32_t* r, uint32_t saddr) {
    asm volatile("ldmatrix.sync.aligned.m8n8.x4.shared.b16 {%0,%1,%2,%3}, [%4];"
                 : "=r"(r[0]), "=r"(r[1]), "=r"(r[2]), "=r"(r[3]) : "r"(saddr));
}
__device__ __forceinline__ void mma16(float* c, const uint32_t* a, const uint32_t* b) {
    asm volatile(
        "mma.sync.aligned.m16n8k16.row.col.f32.f16.f16.f32 "
        "{%0,%1,%2,%3}, {%4,%5,%6,%7}, {%8,%9}, {%0,%1,%2,%3};"
        : "+f"(c[0]), "+f"(c[1]), "+f"(c[2]), "+f"(c[3])
        : "r"(a[0]), "r"(a[1]), "r"(a[2]), "r"(a[3]), "r"(b[0]), "r"(b[1]));
}
__device__ __forceinline__ float tanh_a(float x) {
    float r;
    asm("tanh.approx.f32 %0, %1;" : "=f"(r) : "f"(x));
    return r;
}
__device__ __forceinline__ float fsig(float x) {
    return fmaf(tanh_a(0.5f * x), 0.5f, 0.5f);
}
__device__ __forceinline__ float phase_of(int h) {
    return floorf((float)h / (float)(HH - 1) * 8.0f + 1.0f);
}
__device__ __forceinline__ bool block_active(int h0, float t1) {
    int p0 = (int)phase_of(h0);
    int h1 = h0 + 127; if (h1 > HH - 1) h1 = HH - 1;
    int p1 = (int)phase_of(h1);
#pragma unroll 2
    for (int p = p0; p <= p1; p++)
        if (fmodf(t1, (float)p) < 0.01f) return true;
    return false;
}
__device__ __forceinline__ uint4 cvt8(float4 v0, float4 v1) {
    __half2 h0 = __floats2half2_rn(v0.x, v0.y);
    __half2 h1 = __floats2half2_rn(v0.z, v0.w);
    __half2 h2 = __floats2half2_rn(v1.x, v1.y);
    __half2 h3 = __floats2half2_rn(v1.z, v1.w);
    uint4 o;
    o.x = *(uint32_t*)&h0; o.y = *(uint32_t*)&h1;
    o.z = *(uint32_t*)&h2; o.w = *(uint32_t*)&h3;
    return o;
}

// ---------------- kernel: fused fp32->fp16 conversion (16 elems/thr) + gx ----------------
__global__ void cvt_all_kernel(const float4* __restrict__ wih, const float4* __restrict__ whh,
                               const float4* __restrict__ in,  const float4* __restrict__ hx,
                               uint4* __restrict__ o_wih, uint4* __restrict__ o_whh,
                               uint4* __restrict__ o_in,  uint4* __restrict__ o_hx,
                               const float* __restrict__ G, float* __restrict__ gx_out,
                               const int* __restrict__ tptr) {
    if (blockIdx.x == CVT_BLOCKS) {
        __shared__ float sG[NN * NN];
        __shared__ float den[NN];
        __shared__ float den2[NN];
        int tid = threadIdx.x;
        for (int i = tid; i < NN * NN; i += blockDim.x) sG[i] = G[i];
        __syncthreads();
        if (tid < NN) {
            float s = 0.f;
            for (int j = 0; j < NN; j++) s += fabsf(sG[tid * NN + j]);
            den[tid] = fmaxf(s, EPS);
        }
        __syncthreads();
        for (int i = tid; i < NN * NN; i += blockDim.x) sG[i] = sG[i] / den[i / NN];
        __syncthreads();
        if (tid < NN) {
            float s = 0.f;
            for (int j = 0; j < NN; j++) s += fabsf(sG[tid * NN + j]);
            den2[tid] = fmaxf(s, EPS);
        }
        __syncthreads();
        for (int i = tid; i < NN * NN; i += blockDim.x) {
            float w = sG[i];
            g_gx2[i]  = __float2half2_rn(w);
            gx_out[i] = w / den2[i / NN];
        }
        return;
    }

    int i = blockIdx.x * blockDim.x + threadIdx.x;
    if (i >= N16_TOT) return;
    const float t1 = (float)(*tptr) + 1.0f;
    const float4* s;
    uint4* d;
    int j = i;
    if (j < N16_WIH) {
        int ol = (j >> 4) & (FH - 1);
        int gate = ol >> 10;
        if (gate != 3 && !block_active((ol & 1023) & ~127, t1)) return;
        s = wih; d = o_wih;
    } else {
        j -= N16_WIH;
        if (j < N16_WHH) {
            int ol = (j >> 6) & (FH - 1);
            int gate = ol >> 10;
            if (gate != 3 && !block_active((ol & 1023) & ~127, t1)) return;
            s = whh; d = o_whh;
        } else {
            j -= N16_WHH;
            if (j < N16_IN) { s = in; d = o_in; }
            else { j -= N16_IN; s = hx; d = o_hx; }
        }
    }
    float4 v0 = s[4 * j];
    float4 v1 = s[4 * j + 1];
    float4 v2 = s[4 * j + 2];
    float4 v3 = s[4 * j + 3];
    d[2 * j]     = cvt8(v0, v1);
    d[2 * j + 1] = cvt8(v2, v3);
}

// ---------------- kernel 1: fp16 mma.sync gates GEMM; 1-sync multistage schedule ----------------
__global__ __launch_bounds__(256, 2)
void gates_gemm(const float* __restrict__ bhh, const int* __restrict__ ntypes,
                const int* __restrict__ tptr) {
    const int bo = blockIdx.x * TN;
    {
        const float t1 = (float)(*tptr) + 1.0f;
        const int gate = bo >> 10;
        if (gate != 3 && !block_active(bo & 1023, t1)) return;  // uniform exit
    }

    extern __shared__ char smc[];
    const int tid  = threadIdx.x;
    const int lane = tid & 31;
    const int wid  = tid >> 5;

    const int n  = blockIdx.z;
    const int bm = blockIdx.y * TM;
    const int nt = ntypes[n];
    const __half* wih = g_wih_h + (size_t)nt * FH * II;
    const __half* whh = g_whh_h + (size_t)nt * FH * HH;

    const uint32_t sb = smem_u32(smc);

    const int wm = (wid & 3) * 32;
    const int wn = (wid >> 2) * 64;

    const uint32_t aL = (uint32_t)((((lane >> 3) & 1) * 8 + (lane & 7)) * PADB + (lane >> 4) * 16);
    const uint32_t bL = (uint32_t)((((lane >> 4) & 1) * 8 + (lane & 7)) * PADB + ((lane >> 3) & 1) * 16);

    float acc[2][8][4];
#pragma unroll
    for (int i = 0; i < 2; i++)
#pragma unroll
        for (int j = 0; j < 8; j++)
#pragma unroll
            for (int v = 0; v < 4; v++) acc[i][j][v] = 0.f;

    auto load_stage = [&](int kt, int slot) {
        const int k0 = kt * TK;
        const uint32_t ab = sb + (uint32_t)(slot * STAGE_B);
        const uint32_t bb = ab + (uint32_t)A_STAGE_B;
#pragma unroll
        for (int i = 0; i < 2; i++) {
            int f = tid + i * 256;
            int r = f >> 2, c = f & 3;
            int k = k0 + c * 8;
            const __half* src = (k < II)
                ? g_in_h + ((size_t)(bm + r) * NN + n) * II + k
                : g_hx_h + ((size_t)(bm + r) * NN + n) * HH + (k - II);
            cp16(ab + (uint32_t)(r * PADB + c * 16), src);
        }
#pragma unroll
        for (int i = 0; i < 2; i++) {
            int f = tid + i * 256;
            int r = f >> 2, c = f & 3;
            int k = k0 + c * 8;
            const __half* src = (k < II)
                ? wih + (size_t)(bo + r) * II + k
                : whh + (size_t)(bo + r) * HH + (k - II);
            cp16(bb + (uint32_t)(r * PADB + c * 16), src);
        }
    };

#pragma unroll
    for (int s = 0; s < NSTAGE - 1; s++) {
        load_stage(s, s);
        asm volatile("cp.async.commit_group;" ::: "memory");
    }

    for (int kt = 0; kt < NCHUNK; kt++) {
        asm volatile("cp.async.wait_group %0;" :: "n"(NSTAGE - 2) : "memory");
        __syncthreads();

        const int s = kt % NSTAGE;
        const uint32_t sAb = sb + (uint32_t)(s * STAGE_B);
        const uint32_t sBb = sAb + (uint32_t)A_STAGE_B;

        if (kt + NSTAGE - 1 < NCHUNK)
            load_stage(kt + NSTAGE - 1, (kt + NSTAGE - 1) % NSTAGE);
        asm volatile("cp.async.commit_group;" ::: "memory");

#pragma unroll
        for (int ks = 0; ks < TK / 16; ks++) {
            const uint32_t kb = (uint32_t)(ks * 32);
            uint32_t af[2][4];
#pragma unroll
            for (int mi = 0; mi < 2; mi++)
                ldsm4(af[mi], sAb + (uint32_t)((wm + mi * 16) * PADB) + kb + aL);
            uint32_t bq[4][4];
#pragma unroll
            for (int np = 0; np < 4; np++)
                ldsm4(bq[np], sBb + (uint32_t)((wn + np * 16) * PADB) + kb + bL);
#pragma unroll
            for (int mi = 0; mi < 2; mi++)
#pragma unroll
                for (int ni = 0; ni < 8; ni++)
                    mma16(acc[mi][ni], af[mi], &bq[ni >> 1][(ni & 1) * 2]);
        }
    }

    const int lr = lane >> 2;
    const int lq = lane & 3;
    const float* brow = bhh + (size_t)nt * FH + bo;
#pragma unroll
    for (int mi = 0; mi < 2; mi++) {
        int r0 = wm + mi * 16 + lr;
        __half* out0 = g_gates_h + ((size_t)(bm + r0)     * NN + n) * FH + bo;
        __half* out1 = g_gates_h + ((size_t)(bm + r0 + 8) * NN + n) * FH + bo;
#pragma unroll
        for (int ni = 0; ni < 8; ni++) {
            int col = wn + ni * 8 + lq * 2;
            float2 bv = *(const float2*)(brow + col);
            __half2 v0 = __floats2half2_rn(acc[mi][ni][0] + bv.x, acc[mi][ni][1] + bv.y);
            __half2 v1 = __floats2half2_rn(acc[mi][ni][2] + bv.x, acc[mi][ni][3] + bv.y);
            *(__half2*)(out0 + col) = v0;
            *(__half2*)(out1 + col) = v1;
        }
    }
}

// ---------------- kernel 2a: HEAVY path (mask=1 h only) ----------------
__global__ __launch_bounds__(128)
void pass2_heavy(const float* __restrict__ cx, const int* __restrict__ tptr,
                 float* __restrict__ hy, float* __restrict__ cyo) {
    __shared__ __half2 sgx[NN * NN];
    const int tid = threadIdx.x;
    for (int i = tid; i < NN * NN; i += 128) sgx[i] = g_gx2[i];
    __syncthreads();

    const int b = blockIdx.y;
    const int h = blockIdx.x * 256 + tid * 2;

    const float t1  = (float)(*tptr) + 1.0f;
    const float ph0 = phase_of(h);
    const float ph1 = phase_of(h + 1);
    const float mk0 = (fmodf(t1, ph0) < 0.01f) ? 1.0f : 0.0f;
    const float mk1 = (fmodf(t1, ph1) < 0.01f) ? 1.0f : 0.0f;
    if ((mk0 + mk1) <= 0.f) return;   // light kernel owns this h (warp-uniform)

    const __half* gbase = g_gates_h + (size_t)b * NN * FH + h;

    __half2 rg0[NN], rg1[NN], rg2[NN], rg3[NN];
#pragma unroll
    for (int nI = 0; nI < NN; nI++) {
        const __half* p = gbase + (size_t)nI * FH;
        rg0[nI] = *(const __half2*)(p);
        rg1[nI] = *(const __half2*)(p + HH);
        rg2[nI] = *(const __half2*)(p + 2 * HH);
        rg3[nI] = *(const __half2*)(p + 3 * HH);
    }

#pragma unroll 1
    for (int m = 0; m < NN; m++) {
        const __half2* wrow = &sgx[m * NN];
        __half2 z = __float2half2_rn(0.f);
        __half2 i0 = z, i1 = z, f0 = z, f1 = z, c0 = z, c1 = z, o0 = z, o1 = z;
#pragma unroll
        for (int nI = 0; nI < NN; nI++) {
            __half2 w = wrow[nI];
            if (nI & 1) {
                i1 = __hfma2(w, rg0[nI], i1);
                f1 = __hfma2(w, rg1[nI], f1);
                c1 = __hfma2(w, rg2[nI], c1);
                o1 = __hfma2(w, rg3[nI], o1);
            } else {
                i0 = __hfma2(w, rg0[nI], i0);
                f0 = __hfma2(w, rg1[nI], f0);
                c0 = __hfma2(w, rg2[nI], c0);
                o0 = __hfma2(w, rg3[nI], o0);
            }
        }
        float2 ig = __half22float2(__hadd2(i0, i1));
        float2 fg = __half22float2(__hadd2(f0, f1));
        float2 cg = __half22float2(__hadd2(c0, c1));
        float2 og = __half22float2(__hadd2(o0, o1));

        size_t idx = ((size_t)b * NN + m) * HH + h;
        float2 cxv = __ldcs((const float2*)(cx + idx));

        float isx = fsig(ig.x), isy = fsig(ig.y);
        float fsx = fsig(fg.x), fsy = fsig(fg.y);
        float ctx = tanh_a(cg.x), cty = tanh_a(cg.y);
        float osx = fsig(og.x), osy = fsig(og.y);

        float cyx = mk0 * (fsx * cxv.x + isx * ctx) + (1.0f - mk0) * cxv.x;
        float cyy = mk1 * (fsy * cxv.y + isy * cty) + (1.0f - mk1) * cxv.y;
        float hyx = osx * tanh_a(cyx);
        float hyy = osy * tanh_a(cyy);

        __stcs((float2*)(hy + idx),  make_float2(hyx, hyy));
        __stcs((float2*)(cyo + idx), make_float2(cyx, cyy));
    }
}

// ---------------- kernel 2b: LIGHT path (mask=0 h only; low regs, high occ) ----------------
__global__ __launch_bounds__(128)
void pass2_light(const float* __restrict__ cx, const int* __restrict__ tptr,
                 float* __restrict__ hy, float* __restrict__ cyo) {
    __shared__ __half2 sgx[NN * NN];
    const int tid = threadIdx.x;
    for (int i = tid; i < NN * NN; i += 128) sgx[i] = g_gx2[i];
    __syncthreads();

    const int b = blockIdx.y;
    const int h = blockIdx.x * 256 + tid * 2;

    const float t1  = (float)(*tptr) + 1.0f;
    const float ph0 = phase_of(h);
    const float ph1 = phase_of(h + 1);
    const float mk0 = (fmodf(t1, ph0) < 0.01f) ? 1.0f : 0.0f;
    const float mk1 = (fmodf(t1, ph1) < 0.01f) ? 1.0f : 0.0f;
    if ((mk0 + mk1) > 0.f) return;   // heavy kernel owns this h (warp-uniform)

    const __half* gbase = g_gates_h + (size_t)b * NN * FH + h;

    __half2 rg3[NN];
#pragma unroll
    for (int nI = 0; nI < NN; nI++)
        rg3[nI] = *(const __half2*)(gbase + (size_t)nI * FH + 3 * HH);

#pragma unroll 1
    for (int m = 0; m < NN; m++) {
        const __half2* wrow = &sgx[m * NN];
        __half2 z = __float2half2_rn(0.f);
        __half2 o0 = z, o1 = z;
#pragma unroll
        for (int nI = 0; nI < NN; nI++) {
            __half2 w = wrow[nI];
            if (nI & 1) o1 = __hfma2(w, rg3[nI], o1);
            else        o0 = __hfma2(w, rg3[nI], o0);
        }
        float2 og = __half22float2(__hadd2(o0, o1));

        size_t idx = ((size_t)b * NN + m) * HH + h;
        float2 cxv = __ldcs((const float2*)(cx + idx));

        float hyx = fsig(og.x) * tanh_a(cxv.x);
        float hyy = fsig(og.y) * tanh_a(cxv.y);

        __stcs((float2*)(hy + idx),  make_float2(hyx, hyy));
        __stcs((float2*)(cyo + idx), cxv);
    }
}

// ---------------- launch ----------------
extern "C" void kernel_launch(void* const* d_in, const int* in_sizes, int n_in,
                              void* d_out, int out_size) {
    const float* input  = (const float*)d_in[0];
    const float* hx     = (const float*)d_in[1];
    const float* cx     = (const float*)d_in[2];
    const float* G      = (const float*)d_in[3];
    const float* wih    = (const float*)d_in[4];
    const float* whh    = (const float*)d_in[5];
    const float* bhh    = (const float*)d_in[6];
    const int*   ntypes = (const int*)d_in[7];
    const int*   tptr   = (const int*)d_in[8];

    float* hy  = (float*)d_out;
    float* cy  = hy + (size_t)B * NN * HH;
    float* gxo = cy + (size_t)B * NN * HH;

    cudaFuncSetAttribute(gates_gemm, cudaFuncAttributeMaxDynamicSharedMemorySize, SM_BYTES);

    void *p_wih, *p_whh, *p_in, *p_hx;
    cudaGetSymbolAddress(&p_wih, g_wih_h);
    cudaGetSymbolAddress(&p_whh, g_whh_h);
    cudaGetSymbolAddress(&p_in,  g_in_h);
    cudaGetSymbolAddress(&p_hx,  g_hx_h);

    cvt_all_kernel<<<CVT_BLOCKS + 1, 256>>>(
        (const float4*)wih, (const float4*)whh, (const float4*)input, (const float4*)hx,
        (uint4*)p_wih, (uint4*)p_whh, (uint4*)p_in, (uint4*)p_hx,
        G, gxo, tptr);

    dim3 grid1(FH / TN, B / TM, NN);   // (32, 4, 21)
    gates_gemm<<<grid1, 256, SM_BYTES>>>(bhh, ntypes, tptr);

    dim3 grid2(HH / 256, B);           // (4, 512)
    pass2_light<<<grid2, 128>>>(cx, tptr, hy, cy);
    pass2_heavy<<<grid2, 128>>>(cx, tptr, hy, cy);
}